// round 9
// baseline (speedup 1.0000x reference)
#include <cuda_runtime.h>

// OTAM soft-DTW, exp-domain, warp-autonomous streaming version (phase-split rows).
// dists: [256, 64, 48, 48] f32 -> out: [256, 64] f32
//
// E = exp(-cum/lbda), lbda = 0.5:
//   E_cur[m] = w[m] * (E_prev[m-1] + E_cur[m-1] (+ E_prev[m] at m==1, m==49)),
//   w = exp(-2 d) = exp2(C*d).  Row 0 is a cumprod of w.
//   answer = -0.5*ln(E_final[49]).
//
// One warp per CTA, 32 problems per warp (1 per lane), grid = 512. Private
// 6-stage cp.async ring per warp; only warp-level sync. Row body is
// phase-split: batch LDS -> early refill issue -> batch EX2 -> FFMA chain.

#define LQ 48
#define MQ 48
#define PPW 32                               // problems per warp/CTA
#define PITCH4 13                            // float4 pitch (208 B) -> LDS.128 conflict-free
#define NSTAGES 6
#define STAGE_F4 (PPW * PITCH4)              // 416 float4 = 6656 B per stage
#define SMEM_BYTES (NSTAGES * STAGE_F4 * 16) // 39936 B per CTA

__device__ __forceinline__ float ex2f(float x) {
    float y; asm("ex2.approx.f32 %0, %1;" : "=f"(y) : "f"(x)); return y;
}
__device__ __forceinline__ float lg2f(float x) {
    float y; asm("lg2.approx.f32 %0, %1;" : "=f"(y) : "f"(x)); return y;
}
__device__ __forceinline__ void cp_async16(void* smem_dst, const void* gsrc) {
    unsigned s = (unsigned)__cvta_generic_to_shared(smem_dst);
    asm volatile("cp.async.cg.shared.global [%0], [%1], 16;\n" :: "r"(s), "l"(gsrc) : "memory");
}

extern __shared__ float4 smem4[];

__global__ void __launch_bounds__(32, 1)
otam_kernel(const float* __restrict__ dists, float* __restrict__ out) {
    const int lane = threadIdx.x;
    const int pbase = blockIdx.x * PPW;
    const float* gbase = dists + (size_t)pbase * (LQ * MQ);

    // Precompute staging offsets once: 384 16B chunks/row, 12 per lane.
    // Chunk ch -> problem p = ch/12, segment j = ch%12. Global requests are
    // contiguous 192B per problem-row -> fully coalesced.
    int goff[12];   // float offset into this warp's block (row 0)
    int soff[12];   // float4 slot within a stage
#pragma unroll
    for (int k = 0; k < 12; k++) {
        int ch = lane + k * 32;
        int p = ch / 12;
        int j = ch - p * 12;
        goff[k] = p * (LQ * MQ) + j * 4;
        soff[k] = p * PITCH4 + j;
    }

    // Prologue: fill the ring.
#pragma unroll
    for (int s = 0; s < NSTAGES; s++) {
        float4* sb = smem4 + s * STAGE_F4;
        const float* gr = gbase + s * MQ;
#pragma unroll
        for (int k = 0; k < 12; k++)
            cp_async16(&sb[soff[k]], gr + goff[k]);
        asm volatile("cp.async.commit_group;\n" ::: "memory");
    }

    const float C = -2.885390081777927f;   // -2/ln2 : exp2(C*d) = exp(-2d)
    float E[50];                           // prev-row exp values, E[1..49]
    int buf = 0;

    for (int l = 0; l < LQ; l++) {
        // One (possibly empty) commit per row -> wait_group NSTAGES-1 means
        // the group carrying row l has landed.
        asm volatile("cp.async.wait_group %0;\n" :: "n"(NSTAGES - 1) : "memory");
        __syncwarp();

        // Phase 1: batch-copy the whole row to registers (12 independent LDS.128).
        const float4* rp = smem4 + buf * STAGE_F4 + lane * PITCH4;
        float4 q[12];
#pragma unroll
        for (int j = 0; j < 12; j++) q[j] = rp[j];

        // Phase 2: buffer is drained -> refill it NOW so DRAM stays fed while
        // we compute.
        __syncwarp();
        if (l + NSTAGES < LQ) {
            float4* sb = smem4 + buf * STAGE_F4;
            const float* gr = gbase + (l + NSTAGES) * MQ;
#pragma unroll
            for (int k = 0; k < 12; k++)
                cp_async16(&sb[soff[k]], gr + goff[k]);
        }
        asm volatile("cp.async.commit_group;\n" ::: "memory");  // empty ok

        // Phase 3: batch EX2 -> w[48] (independent, pipelines at MUFU rt).
        float w[48];
#pragma unroll
        for (int j = 0; j < 12; j++) {
            w[4 * j + 0] = ex2f(q[j].x * C);
            w[4 * j + 1] = ex2f(q[j].y * C);
            w[4 * j + 2] = ex2f(q[j].z * C);
            w[4 * j + 3] = ex2f(q[j].w * C);
        }

        // Phase 4: the DP recurrence.
        if (l == 0) {
            float run = 1.f;
#pragma unroll
            for (int m = 0; m < 48; m++) {
                run *= w[m];
                E[m + 1] = run;
            }
            E[49] = E[48];                 // pad column: d = 0 -> w = 1
        } else {
            // m == 1 edge: includes E_prev[1]; diag = c = 1 here.
            float t1 = E[1];
            float c = w[0] * (2.f + t1);
            float diag = t1;
            E[1] = c;
#pragma unroll
            for (int m = 2; m <= 48; m++) {
                float t = E[m];
                float wd = w[m - 1] * diag;      // off-chain
                c = fmaf(w[m - 1], c, wd);       // 1 FFMA on the chain
                diag = t;
                E[m] = c;
            }
            // m == 49 pad column: w = 1, edge includes E_prev[49].
            { float t = E[49]; c = diag + c + t; E[49] = c; }
        }

        buf = (buf + 1 == NSTAGES) ? 0 : buf + 1;
    }

    out[pbase + lane] = -0.34657359027997264f * lg2f(E[49]);
}

extern "C" void kernel_launch(void* const* d_in, const int* in_sizes, int n_in,
                              void* d_out, int out_size) {
    const float* dists = (const float*)d_in[0];
    float* out = (float*)d_out;
    int B = in_sizes[0] / (LQ * MQ);       // 16384 problems
    int grid = B / PPW;                    // 512 CTAs (1 warp each)

    cudaFuncSetAttribute(otam_kernel, cudaFuncAttributeMaxDynamicSharedMemorySize,
                         SMEM_BYTES);
    otam_kernel<<<grid, 32, SMEM_BYTES>>>(dists, out);
}

// round 10
// speedup vs baseline: 1.0128x; 1.0128x over previous
#include <cuda_runtime.h>

// OTAM soft-DTW, exp-domain, warp-autonomous streaming (R8 structure,
// hoisted addressing, 8-deep ring).
// dists: [256, 64, 48, 48] f32 -> out: [256, 64] f32
//
// E = exp(-cum/lbda), lbda = 0.5:
//   E_cur[m] = w[m] * (E_prev[m-1] + E_cur[m-1] (+ E_prev[m] at m==1, m==49)),
//   w = exp(-2 d) = exp2(C*d).  Row 0 is a cumprod of w.
//   answer = -0.5*ln(E_final[49]).
//
// One warp per CTA, 32 problems per warp (1 per lane), grid = 512.
// Private 8-stage cp.async ring per warp; warp-level sync only.

#define LQ 48
#define MQ 48
#define PPW 32                               // problems per warp/CTA
#define PITCH4 13                            // float4 pitch (208 B) -> LDS.128 conflict-free
#define NSTAGES 8
#define STAGE_F4 (PPW * PITCH4)              // 416 float4 = 6656 B per stage
#define STAGE_BYTES (STAGE_F4 * 16)
#define SMEM_BYTES (NSTAGES * STAGE_BYTES)   // 53248 B per CTA

__device__ __forceinline__ float ex2f(float x) {
    float y; asm("ex2.approx.f32 %0, %1;" : "=f"(y) : "f"(x)); return y;
}
__device__ __forceinline__ float lg2f(float x) {
    float y; asm("lg2.approx.f32 %0, %1;" : "=f"(y) : "f"(x)); return y;
}
__device__ __forceinline__ void cp_async16_s(unsigned smem_dst, const void* gsrc) {
    asm volatile("cp.async.cg.shared.global [%0], [%1], 16;\n"
                 :: "r"(smem_dst), "l"(gsrc) : "memory");
}

extern __shared__ float4 smem4[];

__global__ void __launch_bounds__(32, 1)
otam_kernel(const float* __restrict__ dists, float* __restrict__ out) {
    const int lane = threadIdx.x;
    const int pbase = blockIdx.x * PPW;
    const float* gbase = dists + (size_t)pbase * (LQ * MQ);

    // Hoisted staging map (computed ONCE): 384 16B chunks/row, 12 per lane.
    // chunk ch = lane + 32k -> problem p = ch/12, segment j = ch%12.
    // Global side: 192B contiguous per problem-row -> coalesced.
    int   goff[12];      // float offset of chunk k within a row-plane
    unsigned sslot[12];  // smem byte address of chunk k in stage 0
    const unsigned sbase = (unsigned)__cvta_generic_to_shared(smem4);
#pragma unroll
    for (int k = 0; k < 12; k++) {
        int ch = lane + k * 32;
        int p = ch / 12;
        int j = ch - p * 12;
        goff[k]  = p * (LQ * MQ) + j * 4;
        sslot[k] = sbase + (unsigned)(p * PITCH4 + j) * 16u;
    }

    // Prologue: fill the ring.
#pragma unroll
    for (int s = 0; s < NSTAGES; s++) {
        const float* gr = gbase + s * MQ;
        unsigned sb = (unsigned)(s * STAGE_BYTES);
#pragma unroll
        for (int k = 0; k < 12; k++)
            cp_async16_s(sslot[k] + sb, gr + goff[k]);
        asm volatile("cp.async.commit_group;\n" ::: "memory");
    }

    const float C = -2.885390081777927f;   // -2/ln2 : exp2(C*d) = exp(-2d)
    float E[50];                           // prev-row exp values, E[1..49]
    int buf = 0;

    for (int l = 0; l < LQ; l++) {
        // One (possibly empty) commit per row -> wait_group NSTAGES-1 means
        // the group carrying row l has landed.
        asm volatile("cp.async.wait_group %0;\n" :: "n"(NSTAGES - 1) : "memory");
        __syncwarp();                      // other lanes' copies visible

        const float4* rp = smem4 + buf * STAGE_F4 + lane * PITCH4;

        if (l == 0) {
            float run = 1.f;
#pragma unroll
            for (int j = 0; j < 12; j++) {
                float4 q = rp[j];
                run *= ex2f(q.x * C); E[4 * j + 1] = run;
                run *= ex2f(q.y * C); E[4 * j + 2] = run;
                run *= ex2f(q.z * C); E[4 * j + 3] = run;
                run *= ex2f(q.w * C); E[4 * j + 4] = run;
            }
            E[49] = E[48];                 // pad column: d = 0 -> w = 1
        } else {
            float diag = 1.f;              // E_prev[m-1], starts at exp(0)
            float c = 1.f;                 // E_cur[0] = exp(0)
#pragma unroll
            for (int j = 0; j < 12; j++) {
                float4 q = rp[j];
                float w0 = ex2f(q.x * C);
                float w1 = ex2f(q.y * C);
                float w2 = ex2f(q.z * C);
                float w3 = ex2f(q.w * C);
                // 1-FFMA chain: c = fma(w, c, w*diag); w*diag off-chain.
#define CELL(W, MM)                                                  \
                { float t = E[MM]; float wd = (W) * diag;            \
                  c = fmaf((W), c, wd); diag = t; E[MM] = c; }
                if (j == 0) {
                    // m == 1 edge: includes E_prev[1]; diag = c = 1 here.
                    float t = E[1];
                    c = w0 * (2.f + t);
                    diag = t; E[1] = c;
                } else {
                    CELL(w0, 4 * j + 1)
                }
                CELL(w1, 4 * j + 2)
                CELL(w2, 4 * j + 3)
                CELL(w3, 4 * j + 4)
#undef CELL
            }
            // m == 49 pad column: w = 1, edge includes E_prev[49].
            { float t = E[49]; c = diag + c + t; E[49] = c; }
        }

        __syncwarp();                      // all lanes done reading this buffer
        if (l + NSTAGES < LQ) {
            const float* gr = gbase + (l + NSTAGES) * MQ;
            unsigned sb = (unsigned)(buf * STAGE_BYTES);
#pragma unroll
            for (int k = 0; k < 12; k++)
                cp_async16_s(sslot[k] + sb, gr + goff[k]);
        }
        asm volatile("cp.async.commit_group;\n" ::: "memory");  // empty ok

        buf = (buf + 1 == NSTAGES) ? 0 : buf + 1;
    }

    out[pbase + lane] = -0.34657359027997264f * lg2f(E[49]);
}

extern "C" void kernel_launch(void* const* d_in, const int* in_sizes, int n_in,
                              void* d_out, int out_size) {
    const float* dists = (const float*)d_in[0];
    float* out = (float*)d_out;
    int B = in_sizes[0] / (LQ * MQ);       // 16384 problems
    int grid = B / PPW;                    // 512 CTAs (1 warp each)

    cudaFuncSetAttribute(otam_kernel, cudaFuncAttributeMaxDynamicSharedMemorySize,
                         SMEM_BYTES);
    otam_kernel<<<grid, 32, SMEM_BYTES>>>(dists, out);
}

// round 11
// speedup vs baseline: 1.1322x; 1.1178x over previous
#include <cuda_runtime.h>

// OTAM soft-DTW, exp-domain, 2-lane wavefront split.
// dists: [256, 64, 48, 48] f32 -> out: [256, 64] f32
//
// E = exp(-cum/lbda), lbda = 0.5:
//   E_cur[m] = w[m]*(E_prev[m-1] + E_cur[m-1] (+ E_prev[m] at m==1, m==49)),
//   w = exp(-2 d) = exp2(C*d).  Row 0 == general cell with E_prev == 0.
//   answer = -0.5*ln(E_final[49]).
//
// Lane pair (2p, 2p+1) shares problem p: even lane computes m=1..24 of row t,
// odd lane computes m=25..49 of row t-1 (one-row skew). Handoff
// (c[24], E_prev[24]) via shuffle each step. 16 problems/warp -> 1024 warps
// (2x R8's occupancy), 24-cell serial chain per step (half of R8).

#define LQ 48
#define MQ 48
#define PPW 16                               // problems per warp/CTA
#define PSTRIDE (LQ * MQ)                    // 2304 floats per problem
#define PITCH4 13                            // float4 pitch (208 B), conflict-free
#define STAGE_F4 (PPW * PITCH4)              // 208 float4 = 3328 B per stage (1 row)
#define STAGE_BYTES (STAGE_F4 * 16)
#define NS 8
#define SMEM_BYTES (NS * STAGE_BYTES)        // 26624 B per CTA

__device__ __forceinline__ float ex2f(float x) {
    float y; asm("ex2.approx.f32 %0, %1;" : "=f"(y) : "f"(x)); return y;
}
__device__ __forceinline__ float lg2f(float x) {
    float y; asm("lg2.approx.f32 %0, %1;" : "=f"(y) : "f"(x)); return y;
}
__device__ __forceinline__ void cp_async16_s(unsigned smem_dst, const void* gsrc) {
    asm volatile("cp.async.cg.shared.global [%0], [%1], 16;\n"
                 :: "r"(smem_dst), "l"(gsrc) : "memory");
}

extern __shared__ float4 smem4[];

__global__ void __launch_bounds__(32, 1)
otam_kernel(const float* __restrict__ dists, float* __restrict__ out) {
    const int lane = threadIdx.x;
    const int half = lane & 1;               // 0: left half (A), 1: right half (B)
    const int p    = lane >> 1;              // problem index within warp
    const int pbase = blockIdx.x * PPW;
    const float* gbase = dists + (size_t)pbase * PSTRIDE;

    // Staging map: one row = 16 problems x 192B = 192 chunks of 16B, 6/lane.
    // chunk ch = lane + 32k -> problem pp = ch/12, segment j = ch%12.
    int sgo[6]; unsigned sso[6];
    const unsigned sbase = (unsigned)__cvta_generic_to_shared(smem4);
#pragma unroll
    for (int k = 0; k < 6; k++) {
        int ch = lane + k * 32;
        int pp = ch / 12;
        int j  = ch - pp * 12;
        sgo[k] = pp * PSTRIDE + j * 4;       // float offset within a row-plane
        sso[k] = sbase + (unsigned)(pp * PITCH4 + j) * 16u;
    }

    // Prologue: rows 0..NS-1 into stages 0..NS-1 (NS commits).
#pragma unroll
    for (int s = 0; s < NS; s++) {
        const float* gr = gbase + s * MQ;
#pragma unroll
        for (int k = 0; k < 6; k++)
            cp_async16_s(sso[k] + (unsigned)(s * STAGE_BYTES), gr + sgo[k]);
        asm volatile("cp.async.commit_group;\n" ::: "memory");
    }

    const float C = -2.885390081777927f;     // -2/ln2 : exp2(C*d) = exp(-2d)

    // F: A lanes hold E[1..24] in F[0..23]; B lanes hold E[25..49] in F[0..24].
    float F[25];
#pragma unroll
    for (int i = 0; i < 25; i++) F[i] = 0.f;

    float c = 0.f, diag = 0.f;               // chain outputs (handoff source)
    float cin = 0.f, din = 0.f;              // B's received handoff

    // Per-lane read offset inside a stage: A -> bytes 0..95, B -> 96..191.
    const unsigned rdoff = (unsigned)(p * (PITCH4 * 16) + half * 96);
    const char* smem_c = (const char*)smem4;

    int sA = 0;                              // stage holding row t

#pragma unroll 1
    for (int t = 0; t <= LQ; t++) {          // 49 wavefront steps
        // Commits before step t: NS + max(0, t-1); row t is commit index t.
        asm volatile("cp.async.wait_group %0;\n" :: "n"(NS - 2) : "memory");
        __syncwarp();

        int sB = sA + NS - 1; if (sB >= NS) sB -= NS;   // = (t-1) % NS

        bool act = half ? (t >= 1) : (t < LQ);
        if (act) {
            int st = half ? sB : sA;
            const float4* rp = (const float4*)(smem_c + st * STAGE_BYTES + rdoff);
            float4 q0 = rp[0], q1 = rp[1], q2 = rp[2],
                   q3 = rp[3], q4 = rp[4], q5 = rp[5];

            if (half == 0) { c = 1.f; diag = (t == 0) ? 0.f : 1.f; }
            else           { c = cin; diag = din; }

#define CELLR(W, I) { float tt = F[I]; float wd = (W) * diag; \
                      c = fmaf((W), c, wd); diag = tt; F[I] = c; }
            // group 0 (cells 0..3); cell 0: A has the m==1 edge include.
            {
                float w0 = ex2f(q0.x * C), w1 = ex2f(q0.y * C);
                float w2 = ex2f(q0.z * C), w3 = ex2f(q0.w * C);
                {
                    float tt = F[0];
                    float s0 = diag + c;
                    if (!half) s0 += tt;     // m==1 edge (A only)
                    c = w0 * s0; diag = tt; F[0] = c;
                }
                CELLR(w1, 1) CELLR(w2, 2) CELLR(w3, 3)
            }
#define GROUP(Q, B0)                                                   \
            {                                                          \
                float w0 = ex2f((Q).x * C), w1 = ex2f((Q).y * C);      \
                float w2 = ex2f((Q).z * C), w3 = ex2f((Q).w * C);      \
                CELLR(w0, (B0)) CELLR(w1, (B0)+1)                      \
                CELLR(w2, (B0)+2) CELLR(w3, (B0)+3)                    \
            }
            GROUP(q1, 4) GROUP(q2, 8) GROUP(q3, 12) GROUP(q4, 16) GROUP(q5, 20)
#undef GROUP
#undef CELLR
            // B's pad cell m==49: w = 1, edge include E_prev[49].
            if (half) { float tt = F[24]; c = diag + c + tt; F[24] = c; }
        }

        // Handoff: B lane receives (c[24], E_prev[24]) from its A partner,
        // consumed at the NEXT step.
        float nc = __shfl_sync(0xffffffffu, c,    lane & ~1);
        float nd = __shfl_sync(0xffffffffu, diag, lane & ~1);
        if (half) { cin = nc; din = nd; }

        __syncwarp();                        // all reads of stage sB done
        if (t >= 1) {                        // commit at every step >= 1
            int row = t + NS - 1;
            if (row < LQ) {
                const float* gr = gbase + row * MQ;
                unsigned sb = (unsigned)(sB * STAGE_BYTES);
#pragma unroll
                for (int k = 0; k < 6; k++)
                    cp_async16_s(sso[k] + sb, gr + sgo[k]);
            }
            asm volatile("cp.async.commit_group;\n" ::: "memory");
        }

        sA++; if (sA == NS) sA = 0;
    }

    if (half)
        out[pbase + p] = -0.34657359027997264f * lg2f(F[24]);
}

extern "C" void kernel_launch(void* const* d_in, const int* in_sizes, int n_in,
                              void* d_out, int out_size) {
    const float* dists = (const float*)d_in[0];
    float* out = (float*)d_out;
    int B = in_sizes[0] / PSTRIDE;           // 16384 problems
    int grid = B / PPW;                      // 1024 CTAs (1 warp each)

    cudaFuncSetAttribute(otam_kernel, cudaFuncAttributeMaxDynamicSharedMemorySize,
                         SMEM_BYTES);
    otam_kernel<<<grid, 32, SMEM_BYTES>>>(dists, out);
}